// round 2
// baseline (speedup 1.0000x reference)
#include <cuda_runtime.h>

#define NU 200000
#define NI 100000
#define DIM 64
#define NE 3200000

// ---------------- scratch (static __device__, no allocation) ----------------
__device__ int   g_u_cnt[NU];
__device__ int   g_i_cnt[NI];
__device__ int   g_u_off[NU + 1];
__device__ int   g_i_off[NI + 1];
__device__ int   g_u_cur[NU];
__device__ int   g_i_cur[NI];
__device__ int   g_u_bsum[1024];
__device__ int   g_i_bsum[1024];
__device__ int   g_cols_u[NE];
__device__ float g_vals_u[NE];
__device__ int   g_cols_i[NE];
__device__ float g_vals_i[NE];
__device__ __align__(16) float g_hu[(size_t)NU * DIM];
__device__ __align__(16) float g_hi[(size_t)NI * DIM];

// ---------------- CSR build ----------------
__global__ void zero_cnt_kernel(int* __restrict__ u_cnt, int* __restrict__ i_cnt) {
    int i = blockIdx.x * 256 + threadIdx.x;
    if (i < NU) u_cnt[i] = 0;
    if (i < NI) i_cnt[i] = 0;
}

__global__ void hist_kernel(const int* __restrict__ u_idx, const int* __restrict__ i_idx,
                            int* __restrict__ u_cnt, int* __restrict__ i_cnt) {
    int e = blockIdx.x * 256 + threadIdx.x;
    if (e >= NE) return;
    atomicAdd(&u_cnt[u_idx[e]], 1);
    atomicAdd(&i_cnt[i_idx[e]], 1);
}

// per-block exclusive scan of 256 elements; block sums to bsum
__global__ void scanA_kernel(const int* __restrict__ cnt, int* __restrict__ exc,
                             int* __restrict__ bsum, int n) {
    __shared__ int s[256];
    int tid = threadIdx.x;
    int i = blockIdx.x * 256 + tid;
    int v = (i < n) ? cnt[i] : 0;
    s[tid] = v;
    __syncthreads();
    for (int o = 1; o < 256; o <<= 1) {
        int t = (tid >= o) ? s[tid - o] : 0;
        __syncthreads();
        s[tid] += t;
        __syncthreads();
    }
    if (i < n) exc[i] = s[tid] - v;        // exclusive
    if (tid == 255) bsum[blockIdx.x] = s[tid];
}

// single-block exclusive scan of block sums (nb <= 1024)
__global__ void scanB_kernel(int* __restrict__ bsum, int nb) {
    __shared__ int s[1024];
    int tid = threadIdx.x;
    int v = (tid < nb) ? bsum[tid] : 0;
    s[tid] = v;
    __syncthreads();
    for (int o = 1; o < 1024; o <<= 1) {
        int t = (tid >= o) ? s[tid - o] : 0;
        __syncthreads();
        s[tid] += t;
        __syncthreads();
    }
    if (tid < nb) bsum[tid] = s[tid] - v;  // exclusive
}

__global__ void scanC_kernel(int* __restrict__ exc, const int* __restrict__ bsum,
                             int* __restrict__ cur, int n, int total) {
    int i = blockIdx.x * 256 + threadIdx.x;
    if (i < n) {
        int v = exc[i] + bsum[i >> 8];
        exc[i] = v;
        cur[i] = v;
    }
    if (i == 0) exc[n] = total;
}

__global__ void scatter_kernel(const int* __restrict__ u_idx, const int* __restrict__ i_idx,
                               const float* __restrict__ w_u2i, const float* __restrict__ w_i2u,
                               int* __restrict__ u_cur, int* __restrict__ i_cur,
                               int* __restrict__ cols_u, float* __restrict__ vals_u,
                               int* __restrict__ cols_i, float* __restrict__ vals_i) {
    int e = blockIdx.x * 256 + threadIdx.x;
    if (e >= NE) return;
    int u = u_idx[e];
    int it = i_idx[e];
    int pu = atomicAdd(&u_cur[u], 1);
    cols_u[pu] = it;
    vals_u[pu] = w_u2i[e];
    int pi = atomicAdd(&i_cur[it], 1);
    cols_i[pi] = u;
    vals_i[pi] = w_i2u[e];
}

// ---------------- fused layer: SpMM-gather + [128->64] GEMM + ReLU + L2norm ----------------
// one warp per output row; W is [64,128] row-major (y_j = sum_k W[j,k]*x[k], x = [h_self ; neigh])
__global__ void __launch_bounds__(256) layer_kernel(
    const float* __restrict__ h_self, const float* __restrict__ h_other,
    const int* __restrict__ roff, const int* __restrict__ cols,
    const float* __restrict__ vals, const float* __restrict__ W,
    float* __restrict__ out, int R)
{
    __shared__ float Wt[128][66];   // Wt[k][j] = W[j*128+k]; pad 66 -> conflict-free reads
    for (int t = threadIdx.x; t < 64 * 128; t += 256) {
        int j = t >> 7;
        int k = t & 127;
        Wt[k][j] = W[t];            // coalesced global read
    }
    __syncthreads();

    int warp = threadIdx.x >> 5;
    int lane = threadIdx.x & 31;
    int row = blockIdx.x * 8 + warp;
    if (row >= R) return;

    const float2* hs_ptr = (const float2*)h_self;
    const float2* ho_ptr = (const float2*)h_other;

    float2 hs = hs_ptr[(size_t)row * 32 + lane];   // x[2l], x[2l+1]
    float ax = 0.f, ay = 0.f;                      // x[64+2l], x[64+2l+1]

    int e = roff[row];
    int end = roff[row + 1];
    for (; e + 4 <= end; e += 4) {
        int c0 = cols[e], c1 = cols[e + 1], c2 = cols[e + 2], c3 = cols[e + 3];
        float w0 = vals[e], w1 = vals[e + 1], w2 = vals[e + 2], w3 = vals[e + 3];
        float2 v0 = ho_ptr[(size_t)c0 * 32 + lane];
        float2 v1 = ho_ptr[(size_t)c1 * 32 + lane];
        float2 v2 = ho_ptr[(size_t)c2 * 32 + lane];
        float2 v3 = ho_ptr[(size_t)c3 * 32 + lane];
        ax += w0 * v0.x + w1 * v1.x + w2 * v2.x + w3 * v3.x;
        ay += w0 * v0.y + w1 * v1.y + w2 * v2.y + w3 * v3.y;
    }
    for (; e < end; e++) {
        int c = cols[e];
        float w = vals[e];
        float2 v = ho_ptr[(size_t)c * 32 + lane];
        ax += w * v.x;
        ay += w * v.y;
    }

    // dense part: lane computes outputs j = 2*lane, 2*lane+1
    float yx = 0.f, yy = 0.f;
    #pragma unroll
    for (int s = 0; s < 32; s++) {
        float x0 = __shfl_sync(0xffffffffu, hs.x, s);
        float x1 = __shfl_sync(0xffffffffu, hs.y, s);
        float x2 = __shfl_sync(0xffffffffu, ax, s);
        float x3 = __shfl_sync(0xffffffffu, ay, s);
        int k = 2 * s;
        float2 wa = *(const float2*)&Wt[k][2 * lane];
        float2 wb = *(const float2*)&Wt[k + 1][2 * lane];
        float2 wc = *(const float2*)&Wt[64 + k][2 * lane];
        float2 wd = *(const float2*)&Wt[64 + k + 1][2 * lane];
        yx += x0 * wa.x + x1 * wb.x + x2 * wc.x + x3 * wd.x;
        yy += x0 * wa.y + x1 * wb.y + x2 * wc.y + x3 * wd.y;
    }

    yx = fmaxf(yx, 0.f);
    yy = fmaxf(yy, 0.f);
    float ss = yx * yx + yy * yy;
    #pragma unroll
    for (int o = 16; o; o >>= 1) ss += __shfl_xor_sync(0xffffffffu, ss, o);
    float inv = 1.0f / fmaxf(sqrtf(ss), 1e-12f);
    ((float2*)out)[(size_t)row * 32 + lane] = make_float2(yx * inv, yy * inv);
}

// ---------------- launch ----------------
extern "C" void kernel_launch(void* const* d_in, const int* in_sizes, int n_in,
                              void* d_out, int out_size) {
    const float* user_emb = (const float*)d_in[0];
    const float* item_emb = (const float*)d_in[1];
    const float* Wu       = (const float*)d_in[2];   // [2,64,128]
    const float* Wi       = (const float*)d_in[3];
    const int*   u_idx    = (const int*)d_in[4];
    const int*   i_idx    = (const int*)d_in[5];
    const float* w_u2i    = (const float*)d_in[6];
    const float* w_i2u    = (const float*)d_in[7];
    float* out = (float*)d_out;

    void* p;
    int *u_cnt, *i_cnt, *u_off, *i_off, *u_cur, *i_cur, *u_bsum, *i_bsum, *cols_u, *cols_i;
    float *vals_u, *vals_i, *hu, *hi;
    cudaGetSymbolAddress(&p, g_u_cnt);  u_cnt  = (int*)p;
    cudaGetSymbolAddress(&p, g_i_cnt);  i_cnt  = (int*)p;
    cudaGetSymbolAddress(&p, g_u_off);  u_off  = (int*)p;
    cudaGetSymbolAddress(&p, g_i_off);  i_off  = (int*)p;
    cudaGetSymbolAddress(&p, g_u_cur);  u_cur  = (int*)p;
    cudaGetSymbolAddress(&p, g_i_cur);  i_cur  = (int*)p;
    cudaGetSymbolAddress(&p, g_u_bsum); u_bsum = (int*)p;
    cudaGetSymbolAddress(&p, g_i_bsum); i_bsum = (int*)p;
    cudaGetSymbolAddress(&p, g_cols_u); cols_u = (int*)p;
    cudaGetSymbolAddress(&p, g_cols_i); cols_i = (int*)p;
    cudaGetSymbolAddress(&p, g_vals_u); vals_u = (float*)p;
    cudaGetSymbolAddress(&p, g_vals_i); vals_i = (float*)p;
    cudaGetSymbolAddress(&p, g_hu);     hu     = (float*)p;
    cudaGetSymbolAddress(&p, g_hi);     hi     = (float*)p;

    const int EB  = (NE + 255) / 256;        // 12500
    const int UB  = (NU + 255) / 256;        // 782
    const int IB  = (NI + 255) / 256;        // 391

    // CSR build (both directions)
    zero_cnt_kernel<<<UB, 256>>>(u_cnt, i_cnt);
    hist_kernel<<<EB, 256>>>(u_idx, i_idx, u_cnt, i_cnt);
    scanA_kernel<<<UB, 256>>>(u_cnt, u_off, u_bsum, NU);
    scanA_kernel<<<IB, 256>>>(i_cnt, i_off, i_bsum, NI);
    scanB_kernel<<<1, 1024>>>(u_bsum, UB);
    scanB_kernel<<<1, 1024>>>(i_bsum, IB);
    scanC_kernel<<<UB, 256>>>(u_off, u_bsum, u_cur, NU, NE);
    scanC_kernel<<<IB, 256>>>(i_off, i_bsum, i_cur, NI, NE);
    scatter_kernel<<<EB, 256>>>(u_idx, i_idx, w_u2i, w_i2u,
                                u_cur, i_cur, cols_u, vals_u, cols_i, vals_i);

    const int UWB = (NU + 7) / 8;            // 25000 blocks (8 warps = 8 rows/block)
    const int IWB = (NI + 7) / 8;            // 12500

    // layer 0: read input embeddings, write scratch
    layer_kernel<<<UWB, 256>>>(user_emb, item_emb, u_off, cols_u, vals_u,
                               Wu, hu, NU);
    layer_kernel<<<IWB, 256>>>(item_emb, user_emb, i_off, cols_i, vals_i,
                               Wi, hi, NI);
    // layer 1: read scratch, write output (h_u then h_i, concatenated)
    layer_kernel<<<UWB, 256>>>(hu, hi, u_off, cols_u, vals_u,
                               Wu + 64 * 128, out, NU);
    layer_kernel<<<IWB, 256>>>(hi, hu, i_off, cols_i, vals_i,
                               Wi + 64 * 128, out + (size_t)NU * DIM, NI);
}

// round 4
// speedup vs baseline: 1.0672x; 1.0672x over previous
#include <cuda_runtime.h>

#define NU 200000
#define NI 100000
#define DIM 64
#define NE 3200000

// ---------------- scratch (static __device__, no allocation) ----------------
__device__ int   g_u_cnt[NU];
__device__ int   g_i_cnt[NI];
__device__ int   g_u_off[NU + 1];
__device__ int   g_i_off[NI + 1];
__device__ int   g_u_cur[NU];
__device__ int   g_i_cur[NI];
__device__ int   g_u_bsum[1024];
__device__ int   g_i_bsum[1024];
__device__ int   g_cols_u[NE];
__device__ float g_vals_u[NE];
__device__ int   g_cols_i[NE];
__device__ float g_vals_i[NE];
__device__ __align__(16) float g_hu[(size_t)NU * DIM];
__device__ __align__(16) float g_hi[(size_t)NI * DIM];

// ---------------- CSR build ----------------
__global__ void zero_cnt_kernel(int* __restrict__ u_cnt, int* __restrict__ i_cnt) {
    int i = blockIdx.x * 256 + threadIdx.x;
    if (i < NU) u_cnt[i] = 0;
    if (i < NI) i_cnt[i] = 0;
}

__global__ void hist_kernel(const int* __restrict__ u_idx, const int* __restrict__ i_idx,
                            int* __restrict__ u_cnt, int* __restrict__ i_cnt) {
    int e = blockIdx.x * 256 + threadIdx.x;
    if (e >= NE) return;
    atomicAdd(&u_cnt[u_idx[e]], 1);
    atomicAdd(&i_cnt[i_idx[e]], 1);
}

// per-block exclusive scan of 256 elements; block sums to bsum
__global__ void scanA_kernel(const int* __restrict__ cnt, int* __restrict__ exc,
                             int* __restrict__ bsum, int n) {
    __shared__ int s[256];
    int tid = threadIdx.x;
    int i = blockIdx.x * 256 + tid;
    int v = (i < n) ? cnt[i] : 0;
    s[tid] = v;
    __syncthreads();
    for (int o = 1; o < 256; o <<= 1) {
        int t = (tid >= o) ? s[tid - o] : 0;
        __syncthreads();
        s[tid] += t;
        __syncthreads();
    }
    if (i < n) exc[i] = s[tid] - v;        // exclusive
    if (tid == 255) bsum[blockIdx.x] = s[tid];
}

// single-block exclusive scan of block sums (nb <= 1024)
__global__ void scanB_kernel(int* __restrict__ bsum, int nb) {
    __shared__ int s[1024];
    int tid = threadIdx.x;
    int v = (tid < nb) ? bsum[tid] : 0;
    s[tid] = v;
    __syncthreads();
    for (int o = 1; o < 1024; o <<= 1) {
        int t = (tid >= o) ? s[tid - o] : 0;
        __syncthreads();
        s[tid] += t;
        __syncthreads();
    }
    if (tid < nb) bsum[tid] = s[tid] - v;  // exclusive
}

__global__ void scanC_kernel(int* __restrict__ exc, const int* __restrict__ bsum,
                             int* __restrict__ cur, int n, int total) {
    int i = blockIdx.x * 256 + threadIdx.x;
    if (i < n) {
        int v = exc[i] + bsum[i >> 8];
        exc[i] = v;
        cur[i] = v;
    }
    if (i == 0) exc[n] = total;
}

__global__ void scatter_kernel(const int* __restrict__ u_idx, const int* __restrict__ i_idx,
                               const float* __restrict__ w_u2i, const float* __restrict__ w_i2u,
                               int* __restrict__ u_cur, int* __restrict__ i_cur,
                               int* __restrict__ cols_u, float* __restrict__ vals_u,
                               int* __restrict__ cols_i, float* __restrict__ vals_i) {
    int e = blockIdx.x * 256 + threadIdx.x;
    if (e >= NE) return;
    int u = u_idx[e];
    int it = i_idx[e];
    int pu = atomicAdd(&u_cur[u], 1);
    cols_u[pu] = it;
    vals_u[pu] = w_u2i[e];
    int pi = atomicAdd(&i_cur[it], 1);
    cols_i[pi] = u;
    vals_i[pi] = w_i2u[e];
}

// ---------------- fused layer: SpMM-gather + [128->64] GEMM + ReLU + L2norm ----------------
// Persistent grid-stride: W loaded into smem ONCE per block, warps stride over rows.
// W is [64,128] row-major (y_j = sum_k W[j,k]*x[k], x = [h_self ; neigh])
__global__ void __launch_bounds__(256) layer_kernel(
    const float* __restrict__ h_self, const float* __restrict__ h_other,
    const int* __restrict__ roff, const int* __restrict__ cols,
    const float* __restrict__ vals, const float* __restrict__ W,
    float* __restrict__ out, int R)
{
    __shared__ float Wt[128][66];   // Wt[k][j] = W[j*128+k]; pad 66 -> conflict-free reads
    for (int t = threadIdx.x; t < 64 * 128; t += 256) {
        int j = t >> 7;
        int k = t & 127;
        Wt[k][j] = W[t];            // coalesced global read
    }
    __syncthreads();

    int warp = threadIdx.x >> 5;
    int lane = threadIdx.x & 31;
    int wstride = gridDim.x * 8;

    const float2* hs_ptr = (const float2*)h_self;
    const float2* ho_ptr = (const float2*)h_other;

    for (int row = blockIdx.x * 8 + warp; row < R; row += wstride) {
        float2 hs = hs_ptr[(size_t)row * 32 + lane];   // x[2l], x[2l+1]
        float ax = 0.f, ay = 0.f;                      // x[64+2l], x[64+2l+1]

        int e = roff[row];
        int end = roff[row + 1];
        for (; e + 4 <= end; e += 4) {
            int c0 = cols[e], c1 = cols[e + 1], c2 = cols[e + 2], c3 = cols[e + 3];
            float w0 = vals[e], w1 = vals[e + 1], w2 = vals[e + 2], w3 = vals[e + 3];
            float2 v0 = ho_ptr[(size_t)c0 * 32 + lane];
            float2 v1 = ho_ptr[(size_t)c1 * 32 + lane];
            float2 v2 = ho_ptr[(size_t)c2 * 32 + lane];
            float2 v3 = ho_ptr[(size_t)c3 * 32 + lane];
            ax += w0 * v0.x + w1 * v1.x + w2 * v2.x + w3 * v3.x;
            ay += w0 * v0.y + w1 * v1.y + w2 * v2.y + w3 * v3.y;
        }
        for (; e < end; e++) {
            int c = cols[e];
            float w = vals[e];
            float2 v = ho_ptr[(size_t)c * 32 + lane];
            ax += w * v.x;
            ay += w * v.y;
        }

        // dense part: lane computes outputs j = 2*lane, 2*lane+1
        float yx = 0.f, yy = 0.f;
        #pragma unroll
        for (int s = 0; s < 32; s++) {
            float x0 = __shfl_sync(0xffffffffu, hs.x, s);
            float x1 = __shfl_sync(0xffffffffu, hs.y, s);
            float x2 = __shfl_sync(0xffffffffu, ax, s);
            float x3 = __shfl_sync(0xffffffffu, ay, s);
            int k = 2 * s;
            float2 wa = *(const float2*)&Wt[k][2 * lane];
            float2 wb = *(const float2*)&Wt[k + 1][2 * lane];
            float2 wc = *(const float2*)&Wt[64 + k][2 * lane];
            float2 wd = *(const float2*)&Wt[64 + k + 1][2 * lane];
            yx += x0 * wa.x + x1 * wb.x + x2 * wc.x + x3 * wd.x;
            yy += x0 * wa.y + x1 * wb.y + x2 * wc.y + x3 * wd.y;
        }

        yx = fmaxf(yx, 0.f);
        yy = fmaxf(yy, 0.f);
        float ss = yx * yx + yy * yy;
        #pragma unroll
        for (int o = 16; o; o >>= 1) ss += __shfl_xor_sync(0xffffffffu, ss, o);
        float inv = 1.0f / fmaxf(sqrtf(ss), 1e-12f);
        ((float2*)out)[(size_t)row * 32 + lane] = make_float2(yx * inv, yy * inv);
    }
}

// ---------------- launch ----------------
extern "C" void kernel_launch(void* const* d_in, const int* in_sizes, int n_in,
                              void* d_out, int out_size) {
    const float* user_emb = (const float*)d_in[0];
    const float* item_emb = (const float*)d_in[1];
    const float* Wu       = (const float*)d_in[2];   // [2,64,128]
    const float* Wi       = (const float*)d_in[3];
    const int*   u_idx    = (const int*)d_in[4];
    const int*   i_idx    = (const int*)d_in[5];
    const float* w_u2i    = (const float*)d_in[6];
    const float* w_i2u    = (const float*)d_in[7];
    float* out = (float*)d_out;

    void* p;
    int *u_cnt, *i_cnt, *u_off, *i_off, *u_cur, *i_cur, *u_bsum, *i_bsum, *cols_u, *cols_i;
    float *vals_u, *vals_i, *hu, *hi;
    cudaGetSymbolAddress(&p, g_u_cnt);  u_cnt  = (int*)p;
    cudaGetSymbolAddress(&p, g_i_cnt);  i_cnt  = (int*)p;
    cudaGetSymbolAddress(&p, g_u_off);  u_off  = (int*)p;
    cudaGetSymbolAddress(&p, g_i_off);  i_off  = (int*)p;
    cudaGetSymbolAddress(&p, g_u_cur);  u_cur  = (int*)p;
    cudaGetSymbolAddress(&p, g_i_cur);  i_cur  = (int*)p;
    cudaGetSymbolAddress(&p, g_u_bsum); u_bsum = (int*)p;
    cudaGetSymbolAddress(&p, g_i_bsum); i_bsum = (int*)p;
    cudaGetSymbolAddress(&p, g_cols_u); cols_u = (int*)p;
    cudaGetSymbolAddress(&p, g_cols_i); cols_i = (int*)p;
    cudaGetSymbolAddress(&p, g_vals_u); vals_u = (float*)p;
    cudaGetSymbolAddress(&p, g_vals_i); vals_i = (float*)p;
    cudaGetSymbolAddress(&p, g_hu);     hu     = (float*)p;
    cudaGetSymbolAddress(&p, g_hi);     hi     = (float*)p;

    const int EB  = (NE + 255) / 256;        // 12500
    const int UB  = (NU + 255) / 256;        // 782
    const int IB  = (NI + 255) / 256;        // 391

    // CSR build (both directions)
    zero_cnt_kernel<<<UB, 256>>>(u_cnt, i_cnt);
    hist_kernel<<<EB, 256>>>(u_idx, i_idx, u_cnt, i_cnt);
    scanA_kernel<<<UB, 256>>>(u_cnt, u_off, u_bsum, NU);
    scanA_kernel<<<IB, 256>>>(i_cnt, i_off, i_bsum, NI);
    scanB_kernel<<<1, 1024>>>(u_bsum, UB);
    scanB_kernel<<<1, 1024>>>(i_bsum, IB);
    scanC_kernel<<<UB, 256>>>(u_off, u_bsum, u_cur, NU, NE);
    scanC_kernel<<<IB, 256>>>(i_off, i_bsum, i_cur, NI, NE);
    scatter_kernel<<<EB, 256>>>(u_idx, i_idx, w_u2i, w_i2u,
                                u_cur, i_cur, cols_u, vals_u, cols_i, vals_i);

    // persistent layer kernels: 152 SMs * 6 blocks (smem-limited occupancy)
    const int PG = 152 * 6;   // 912 blocks, 8 warps each

    // layer 0: read input embeddings, write scratch
    layer_kernel<<<PG, 256>>>(user_emb, item_emb, u_off, cols_u, vals_u,
                              Wu, hu, NU);
    layer_kernel<<<PG, 256>>>(item_emb, user_emb, i_off, cols_i, vals_i,
                              Wi, hi, NI);
    // layer 1: read scratch, write output (h_u then h_i, concatenated)
    layer_kernel<<<PG, 256>>>(hu, hi, u_off, cols_u, vals_u,
                              Wu + 64 * 128, out, NU);
    layer_kernel<<<PG, 256>>>(hi, hu, i_off, cols_i, vals_i,
                              Wi + 64 * 128, out + (size_t)NU * DIM, NI);
}